// round 2
// baseline (speedup 1.0000x reference)
#include <cuda_runtime.h>

#define IN_CH 65
#define HID   64
#define MAX_NODES 100000

// Scratch: transformed neighbor features y = x @ W_rel^T  (row-aligned to 256B)
__device__ float g_y[(size_t)MAX_NODES * HID];

// ---------------------------------------------------------------------------
// Kernel 1: per-node dual matvec.
//   g_y[n]  = W_rel  @ x[n]
//   out[n]  = W_root @ x[n] + b_rel   (scatter kernel then accumulates into out)
// 64 threads/block, thread o owns output channel o; both weight columns live
// in registers (~130 regs), x row staged in smem and broadcast.
// ---------------------------------------------------------------------------
__global__ __launch_bounds__(64, 4) void transform_kernel(
    const float* __restrict__ x,
    const float* __restrict__ W_rel,
    const float* __restrict__ b_rel,
    const float* __restrict__ W_root,
    float* __restrict__ out,
    int n_nodes)
{
    const int o = threadIdx.x;  // 0..63 output channel

    float wr[IN_CH], wo[IN_CH];
#pragma unroll
    for (int k = 0; k < IN_CH; ++k) {
        wr[k] = W_rel[o * IN_CH + k];
        wo[k] = W_root[o * IN_CH + k];
    }
    const float bias = b_rel[o];

    __shared__ float sx[IN_CH];

    for (int n = blockIdx.x; n < n_nodes; n += gridDim.x) {
        const float* xr = x + (size_t)n * IN_CH;
        sx[o] = xr[o];
        if (o == 0) sx[64] = xr[64];
        __syncthreads();

        float ay = 0.0f;
        float ao = bias;
#pragma unroll
        for (int k = 0; k < IN_CH; ++k) {
            const float xk = sx[k];
            ay = fmaf(wr[k], xk, ay);
            ao = fmaf(wo[k], xk, ao);
        }
        g_y[(size_t)n * HID + o]  = ay;
        out[(size_t)n * HID + o]  = ao;
        __syncthreads();  // protect sx before next iteration's overwrite
    }
}

// ---------------------------------------------------------------------------
// Kernel 2: edge scatter. One thread per (edge, 4-channel chunk): 16 chunks
// cover 64 channels. Gather float4 from g_y[src] (L2-resident), scale by
// edge weight, vector-reduce into out[dst] via red.global.add.v4.f32.
// Warp layout: lanes 0..15 -> edge e chunks 0..15 (fully coalesced 256B row),
// lanes 16..31 -> edge e+1.
// edge_index arrives as INT32 (harness downcasts the reference's int64).
// ---------------------------------------------------------------------------
__global__ void scatter_kernel(
    const int* __restrict__ ei,         // [2, E] int32: row0 = src, row1 = dst
    const float* __restrict__ ew,       // [E]
    float* __restrict__ out,            // [N, 64]
    int E)
{
    const int i = blockIdx.x * blockDim.x + threadIdx.x;
    const int total = E * 16;
    if (i >= total) return;

    const int e = i >> 4;
    const int c = i & 15;

    const int src = __ldg(ei + e);
    const int dst = __ldg(ei + E + e);
    const float w = __ldg(ew + e);

    const float4 v = *reinterpret_cast<const float4*>(g_y + (size_t)src * HID + c * 4);

    float* p = out + (size_t)dst * HID + c * 4;
    asm volatile(
        "red.global.add.v4.f32 [%0], {%1, %2, %3, %4};"
        :: "l"(p), "f"(v.x * w), "f"(v.y * w), "f"(v.z * w), "f"(v.w * w)
        : "memory");
}

// ---------------------------------------------------------------------------
extern "C" void kernel_launch(void* const* d_in, const int* in_sizes, int n_in,
                              void* d_out, int out_size)
{
    const float* x      = (const float*)d_in[0];
    const int*   ei     = (const int*)d_in[1];
    const float* ew     = (const float*)d_in[2];
    const float* W_rel  = (const float*)d_in[3];
    const float* b_rel  = (const float*)d_in[4];
    const float* W_root = (const float*)d_in[5];
    float*       out    = (float*)d_out;

    const int n_nodes = in_sizes[0] / IN_CH;
    const int E       = in_sizes[1] / 2;   // edge_index is [2, E]

    // Kernel 1: init out = W_root @ x + b, and y = W_rel @ x
    transform_kernel<<<2048, 64>>>(x, W_rel, b_rel, W_root, out, n_nodes);

    // Kernel 2: out[dst] += w_e * y[src]
    const int total  = E * 16;
    const int blocks = (total + 255) / 256;
    scatter_kernel<<<blocks, 256>>>(ei, ew, out, E);
}